// round 6
// baseline (speedup 1.0000x reference)
#include <cuda_runtime.h>

#define N_NODES 100000
#define N_EDGES 1600000
#define F_IN 32
#define HID 16

// Scratch (no allocations allowed in kernel_launch)
__device__ __align__(16) float g_xt  [N_NODES * HID];   // x @ W1_l.T
__device__ __align__(16) float g_xr1 [N_NODES * HID];   // x @ W1_r.T
__device__ __align__(16) float g_h   [N_NODES * HID];   // relu(layer1)
__device__ __align__(16) float g_agg [N_NODES * HID];   // layer-2 mean aggregate
__device__ int g_degi  [N_NODES];       // in-degree (int)
__device__ int g_rowoff[N_NODES + 1];   // CSR offsets
__device__ int g_cursor[N_NODES];       // fill cursors
__device__ int g_adj   [N_EDGES];       // src per dst bucket

// ---------------------------------------------------------------------------
// 1) k_pre: per node — zero degree, xt = x@W1l.T, xr1 = x@W1r.T
// ---------------------------------------------------------------------------
__global__ void __launch_bounds__(256) k_pre(const float* __restrict__ x,
                                             const float* __restrict__ W1l,
                                             const float* __restrict__ W1r) {
    __shared__ float Wl[HID * F_IN];
    __shared__ float Wr[HID * F_IN];
    for (int i = threadIdx.x; i < HID * F_IN; i += blockDim.x) {
        Wl[i] = W1l[i];
        Wr[i] = W1r[i];
    }
    __syncthreads();

    int n = blockIdx.x * blockDim.x + threadIdx.x;
    if (n >= N_NODES) return;

    g_degi[n] = 0;

    float xr[F_IN];
    const float4* xp = reinterpret_cast<const float4*>(x + (size_t)n * F_IN);
#pragma unroll
    for (int q = 0; q < F_IN / 4; q++) {
        float4 v = xp[q];
        xr[4*q+0] = v.x; xr[4*q+1] = v.y; xr[4*q+2] = v.z; xr[4*q+3] = v.w;
    }

    float4* op_t = reinterpret_cast<float4*>(g_xt  + (size_t)n * HID);
    float4* op_r = reinterpret_cast<float4*>(g_xr1 + (size_t)n * HID);
#pragma unroll
    for (int og = 0; og < HID / 4; og++) {
        float4 rt, rr;
        float* rtp = &rt.x;
        float* rrp = &rr.x;
#pragma unroll
        for (int oo = 0; oo < 4; oo++) {
            int o = og * 4 + oo;
            float at = 0.0f, ar = 0.0f;
#pragma unroll
            for (int k = 0; k < F_IN; k++) {
                at += xr[k] * Wl[o * F_IN + k];
                ar += xr[k] * Wr[o * F_IN + k];
            }
            rtp[oo] = at;
            rrp[oo] = ar;
        }
        op_t[og] = rt;
        op_r[og] = rr;
    }
}

// ---------------------------------------------------------------------------
// 2) count in-degrees
// ---------------------------------------------------------------------------
__global__ void k_count(const int* __restrict__ ei) {
    int e = blockIdx.x * blockDim.x + threadIdx.x;
    if (e >= N_EDGES) return;
    atomicAdd(&g_degi[__ldg(ei + N_EDGES + e)], 1);
}

// ---------------------------------------------------------------------------
// 3) exclusive scan of degrees -> row offsets + cursors (single block)
// ---------------------------------------------------------------------------
__global__ void __launch_bounds__(1024) k_scan() {
    __shared__ int sums[1024];
    const int T = 1024;
    const int CH = (N_NODES + T - 1) / T;   // 98
    int tid = threadIdx.x;
    int base = tid * CH;
    int end  = min(base + CH, N_NODES);

    int s = 0;
    for (int i = base; i < end; i++) s += g_degi[i];
    sums[tid] = s;
    __syncthreads();

    // inclusive Hillis-Steele scan in smem
    for (int off = 1; off < T; off <<= 1) {
        int v = (tid >= off) ? sums[tid - off] : 0;
        __syncthreads();
        sums[tid] += v;
        __syncthreads();
    }

    int run = (tid == 0) ? 0 : sums[tid - 1];
    for (int i = base; i < end; i++) {
        g_rowoff[i] = run;
        g_cursor[i] = run;
        run += g_degi[i];
    }
    if (tid == T - 1) g_rowoff[N_NODES] = sums[T - 1];
}

// ---------------------------------------------------------------------------
// 4) fill adjacency buckets
// ---------------------------------------------------------------------------
__global__ void k_fill(const int* __restrict__ ei) {
    int e = blockIdx.x * blockDim.x + threadIdx.x;
    if (e >= N_EDGES) return;
    int s = __ldg(ei + e);
    int d = __ldg(ei + N_EDGES + e);
    int pos = atomicAdd(&g_cursor[d], 1);
    g_adj[pos] = s;
}

// ---------------------------------------------------------------------------
// 5) gather layer 1: h = relu(mean_j xt[adj] + b1 + xr1)   (4 threads/node)
// ---------------------------------------------------------------------------
__global__ void k_gather1(const float* __restrict__ b1) {
    unsigned t = blockIdx.x * blockDim.x + threadIdx.x;
    unsigned n = t >> 2;
    unsigned q = t & 3;
    if (n >= N_NODES) return;

    int beg = __ldg(&g_rowoff[n]);
    int end = __ldg(&g_rowoff[n + 1]);

    float4 acc = make_float4(0.f, 0.f, 0.f, 0.f);
    for (int j = beg; j < end; j++) {
        int s = __ldg(&g_adj[j]);
        float4 v = *reinterpret_cast<const float4*>(g_xt + (size_t)s * HID + q * 4);
        acc.x += v.x; acc.y += v.y; acc.z += v.z; acc.w += v.w;
    }
    float inv = 1.0f / fmaxf((float)(end - beg), 1.0f);

    float4 b = __ldg(reinterpret_cast<const float4*>(b1) + q);
    float4 r = *reinterpret_cast<const float4*>(g_xr1 + (size_t)n * HID + q * 4);

    float4 o;
    o.x = fmaxf(acc.x * inv + b.x + r.x, 0.0f);
    o.y = fmaxf(acc.y * inv + b.y + r.y, 0.0f);
    o.z = fmaxf(acc.z * inv + b.z + r.z, 0.0f);
    o.w = fmaxf(acc.w * inv + b.w + r.w, 0.0f);
    *reinterpret_cast<float4*>(g_h + (size_t)n * HID + q * 4) = o;
}

// ---------------------------------------------------------------------------
// 6) gather layer 2: agg = mean_j h[adj]   (4 threads/node)
// ---------------------------------------------------------------------------
__global__ void k_gather2() {
    unsigned t = blockIdx.x * blockDim.x + threadIdx.x;
    unsigned n = t >> 2;
    unsigned q = t & 3;
    if (n >= N_NODES) return;

    int beg = __ldg(&g_rowoff[n]);
    int end = __ldg(&g_rowoff[n + 1]);

    float4 acc = make_float4(0.f, 0.f, 0.f, 0.f);
    for (int j = beg; j < end; j++) {
        int s = __ldg(&g_adj[j]);
        float4 v = *reinterpret_cast<const float4*>(g_h + (size_t)s * HID + q * 4);
        acc.x += v.x; acc.y += v.y; acc.z += v.z; acc.w += v.w;
    }
    float inv = 1.0f / fmaxf((float)(end - beg), 1.0f);
    acc.x *= inv; acc.y *= inv; acc.z *= inv; acc.w *= inv;
    *reinterpret_cast<float4*>(g_agg + (size_t)n * HID + q * 4) = acc;
}

// ---------------------------------------------------------------------------
// 7) out = agg @ W2_l.T + b2 + h @ W2_r.T
// ---------------------------------------------------------------------------
__global__ void __launch_bounds__(256) k_node2(float* __restrict__ out,
                        const float* __restrict__ W2l,
                        const float* __restrict__ b2,
                        const float* __restrict__ W2r) {
    __shared__ float Wl[F_IN * HID];
    __shared__ float Wr[F_IN * HID];
    __shared__ float bs[F_IN];
    for (int i = threadIdx.x; i < F_IN * HID; i += blockDim.x) {
        Wl[i] = W2l[i];
        Wr[i] = W2r[i];
    }
    if (threadIdx.x < F_IN) bs[threadIdx.x] = b2[threadIdx.x];
    __syncthreads();

    int n = blockIdx.x * blockDim.x + threadIdx.x;
    if (n >= N_NODES) return;

    float hr[HID], ar[HID];
    const float4* hp = reinterpret_cast<const float4*>(g_h   + (size_t)n * HID);
    const float4* ap = reinterpret_cast<const float4*>(g_agg + (size_t)n * HID);
#pragma unroll
    for (int q = 0; q < HID / 4; q++) {
        float4 v = hp[q];
        hr[4*q+0] = v.x; hr[4*q+1] = v.y; hr[4*q+2] = v.z; hr[4*q+3] = v.w;
        float4 a = ap[q];
        ar[4*q+0] = a.x; ar[4*q+1] = a.y; ar[4*q+2] = a.z; ar[4*q+3] = a.w;
    }

    float4* op = reinterpret_cast<float4*>(out + (size_t)n * F_IN);
#pragma unroll
    for (int fg = 0; fg < F_IN / 4; fg++) {
        float4 r;
        float* rp = &r.x;
#pragma unroll
        for (int ff = 0; ff < 4; ff++) {
            int f = fg * 4 + ff;
            float acc = bs[f];
#pragma unroll
            for (int k = 0; k < HID; k++) {
                acc += ar[k] * Wl[f * HID + k] + hr[k] * Wr[f * HID + k];
            }
            rp[ff] = acc;
        }
        op[fg] = r;
    }
}

// ---------------------------------------------------------------------------
extern "C" void kernel_launch(void* const* d_in, const int* in_sizes, int n_in,
                              void* d_out, int out_size) {
    const float* x   = (const float*)d_in[0];
    const int*   ei  = (const int*)d_in[1];   // [1,2,E], int32 (JAX x64 off)
    const float* W1l = (const float*)d_in[2];
    const float* b1  = (const float*)d_in[3];
    const float* W1r = (const float*)d_in[4];
    const float* W2l = (const float*)d_in[5];
    const float* b2  = (const float*)d_in[6];
    const float* W2r = (const float*)d_in[7];
    float*       out = (float*)d_out;

    const int T = 256;
    const int grid_node  = (N_NODES + T - 1) / T;
    const int grid_node4 = (N_NODES * 4 + T - 1) / T;
    const int grid_edge  = (N_EDGES + T - 1) / T;

    k_pre    <<<grid_node,  T>>>(x, W1l, W1r);
    k_count  <<<grid_edge,  T>>>(ei);
    k_scan   <<<1, 1024>>>();
    k_fill   <<<grid_edge,  T>>>(ei);
    k_gather1<<<grid_node4, T>>>(b1);
    k_gather2<<<grid_node4, T>>>();
    k_node2  <<<grid_node,  T>>>(out, W2l, b2, W2r);
}

// round 7
// speedup vs baseline: 1.5303x; 1.5303x over previous
#include <cuda_runtime.h>

#define N_NODES 100000
#define N_EDGES 1600000
#define F_IN 32
#define HID 16

// Scratch (no allocations allowed in kernel_launch)
__device__ __align__(16) float g_deg [N_NODES];
__device__ __align__(16) float g_xt  [N_NODES * HID];   // x @ W1_l.T
__device__ __align__(16) float g_xr1 [N_NODES * HID];   // x @ W1_r.T
__device__ __align__(16) float g_sum1[N_NODES * HID];   // scatter target layer 1
__device__ __align__(16) float g_h   [N_NODES * HID];   // relu(layer1)
__device__ __align__(16) float g_sumh[N_NODES * HID];   // scatter target layer 2

__device__ __forceinline__ void red_add_v4(float* addr, float4 v) {
    asm volatile("red.global.add.v4.f32 [%0], {%1,%2,%3,%4};"
                 :: "l"(addr), "f"(v.x), "f"(v.y), "f"(v.z), "f"(v.w)
                 : "memory");
}

// ---------------------------------------------------------------------------
// 1) k_pre: 4 threads/node. Zero scratch rows; thread q computes outputs
//    [4q,4q+4) of xt = x@W1l.T and xr1 = x@W1r.T.
// ---------------------------------------------------------------------------
__global__ void __launch_bounds__(256) k_pre(const float* __restrict__ x,
                                             const float* __restrict__ W1l,
                                             const float* __restrict__ W1r) {
    __shared__ float Wl[HID * F_IN];
    __shared__ float Wr[HID * F_IN];
    for (int i = threadIdx.x; i < HID * F_IN; i += blockDim.x) {
        Wl[i] = W1l[i];
        Wr[i] = W1r[i];
    }
    __syncthreads();

    unsigned t = blockIdx.x * blockDim.x + threadIdx.x;
    unsigned n = t >> 2;
    unsigned q = t & 3;
    if (n >= N_NODES) return;

    if (q == 0) g_deg[n] = 0.0f;
    float4 z = make_float4(0.f, 0.f, 0.f, 0.f);
    *reinterpret_cast<float4*>(g_sum1 + (size_t)n * HID + q * 4) = z;
    *reinterpret_cast<float4*>(g_sumh + (size_t)n * HID + q * 4) = z;

    float xr[F_IN];
    const float4* xp = reinterpret_cast<const float4*>(x + (size_t)n * F_IN);
#pragma unroll
    for (int g = 0; g < F_IN / 4; g++) {
        float4 v = __ldg(xp + g);
        xr[4*g+0] = v.x; xr[4*g+1] = v.y; xr[4*g+2] = v.z; xr[4*g+3] = v.w;
    }

    float4 rt, rr;
    float* rtp = &rt.x;
    float* rrp = &rr.x;
#pragma unroll
    for (int oo = 0; oo < 4; oo++) {
        int o = q * 4 + oo;
        float at = 0.0f, ar = 0.0f;
#pragma unroll
        for (int k = 0; k < F_IN; k++) {
            at += xr[k] * Wl[o * F_IN + k];
            ar += xr[k] * Wr[o * F_IN + k];
        }
        rtp[oo] = at;
        rrp[oo] = ar;
    }
    *reinterpret_cast<float4*>(g_xt  + (size_t)n * HID + q * 4) = rt;
    *reinterpret_cast<float4*>(g_xr1 + (size_t)n * HID + q * 4) = rr;
}

// ---------------------------------------------------------------------------
// 2) edge scatter layer 1: sum1[dst] += xt[src]; deg[dst] += 1
//    4 threads per edge, one red.v4 each.
// ---------------------------------------------------------------------------
__global__ void k_scatter1(const int* __restrict__ ei) {
    unsigned t = blockIdx.x * blockDim.x + threadIdx.x;
    unsigned e = t >> 2;
    unsigned q = t & 3;
    if (e >= N_EDGES) return;
    int s = __ldg(ei + e);
    int d = __ldg(ei + N_EDGES + e);

    if (q == 0) atomicAdd(&g_deg[d], 1.0f);

    float4 v = *reinterpret_cast<const float4*>(g_xt + (size_t)s * HID + q * 4);
    red_add_v4(g_sum1 + (size_t)d * HID + q * 4, v);
}

// ---------------------------------------------------------------------------
// 3) h = relu(sum1/max(deg,1) + b1 + xr1)   — pure elementwise, quad/node
// ---------------------------------------------------------------------------
__global__ void k_node1(const float* __restrict__ b1) {
    unsigned t = blockIdx.x * blockDim.x + threadIdx.x;
    unsigned n = t >> 2;
    unsigned q = t & 3;
    if (n >= N_NODES) return;

    float inv = 1.0f / fmaxf(__ldg(&g_deg[n]), 1.0f);
    float4 s = *reinterpret_cast<const float4*>(g_sum1 + (size_t)n * HID + q * 4);
    float4 r = *reinterpret_cast<const float4*>(g_xr1  + (size_t)n * HID + q * 4);
    float4 b = __ldg(reinterpret_cast<const float4*>(b1) + q);

    float4 o;
    o.x = fmaxf(s.x * inv + b.x + r.x, 0.0f);
    o.y = fmaxf(s.y * inv + b.y + r.y, 0.0f);
    o.z = fmaxf(s.z * inv + b.z + r.z, 0.0f);
    o.w = fmaxf(s.w * inv + b.w + r.w, 0.0f);
    *reinterpret_cast<float4*>(g_h + (size_t)n * HID + q * 4) = o;
}

// ---------------------------------------------------------------------------
// 4) edge scatter layer 2: sumh[dst] += h[src]  (4 threads per edge)
// ---------------------------------------------------------------------------
__global__ void k_scatter2(const int* __restrict__ ei) {
    unsigned t = blockIdx.x * blockDim.x + threadIdx.x;
    unsigned e = t >> 2;
    unsigned q = t & 3;
    if (e >= N_EDGES) return;
    int s = __ldg(ei + e);
    int d = __ldg(ei + N_EDGES + e);

    float4 v = *reinterpret_cast<const float4*>(g_h + (size_t)s * HID + q * 4);
    red_add_v4(g_sumh + (size_t)d * HID + q * 4, v);
}

// ---------------------------------------------------------------------------
// 5) k_node2: 4 threads/node; thread q computes outputs [8q, 8q+8) of
//    out = (sumh*inv) @ W2_l.T + b2 + h @ W2_r.T
// ---------------------------------------------------------------------------
__global__ void __launch_bounds__(256) k_node2(float* __restrict__ out,
                        const float* __restrict__ W2l,
                        const float* __restrict__ b2,
                        const float* __restrict__ W2r) {
    __shared__ float Wl[F_IN * HID];
    __shared__ float Wr[F_IN * HID];
    __shared__ float bs[F_IN];
    for (int i = threadIdx.x; i < F_IN * HID; i += blockDim.x) {
        Wl[i] = W2l[i];
        Wr[i] = W2r[i];
    }
    if (threadIdx.x < F_IN) bs[threadIdx.x] = b2[threadIdx.x];
    __syncthreads();

    unsigned t = blockIdx.x * blockDim.x + threadIdx.x;
    unsigned n = t >> 2;
    unsigned q = t & 3;
    if (n >= N_NODES) return;

    float inv = 1.0f / fmaxf(g_deg[n], 1.0f);

    float hr[HID], ar[HID];
    const float4* hp = reinterpret_cast<const float4*>(g_h    + (size_t)n * HID);
    const float4* ap = reinterpret_cast<const float4*>(g_sumh + (size_t)n * HID);
#pragma unroll
    for (int g = 0; g < HID / 4; g++) {
        float4 v = hp[g];
        hr[4*g+0] = v.x; hr[4*g+1] = v.y; hr[4*g+2] = v.z; hr[4*g+3] = v.w;
        float4 a = ap[g];
        ar[4*g+0] = a.x * inv; ar[4*g+1] = a.y * inv;
        ar[4*g+2] = a.z * inv; ar[4*g+3] = a.w * inv;
    }

    float4* op = reinterpret_cast<float4*>(out + (size_t)n * F_IN + q * 8);
#pragma unroll
    for (int fg = 0; fg < 2; fg++) {
        float4 r;
        float* rp = &r.x;
#pragma unroll
        for (int ff = 0; ff < 4; ff++) {
            int f = q * 8 + fg * 4 + ff;
            float acc = bs[f];
#pragma unroll
            for (int k = 0; k < HID; k++) {
                acc += ar[k] * Wl[f * HID + k] + hr[k] * Wr[f * HID + k];
            }
            rp[ff] = acc;
        }
        op[fg] = r;
    }
}

// ---------------------------------------------------------------------------
extern "C" void kernel_launch(void* const* d_in, const int* in_sizes, int n_in,
                              void* d_out, int out_size) {
    const float* x   = (const float*)d_in[0];
    const int*   ei  = (const int*)d_in[1];   // [1,2,E], int32 (JAX x64 off)
    const float* W1l = (const float*)d_in[2];
    const float* b1  = (const float*)d_in[3];
    const float* W1r = (const float*)d_in[4];
    const float* W2l = (const float*)d_in[5];
    const float* b2  = (const float*)d_in[6];
    const float* W2r = (const float*)d_in[7];
    float*       out = (float*)d_out;

    const int T = 256;
    const int grid_node4 = (N_NODES * 4 + T - 1) / T;
    const int grid_edge4 = ((N_EDGES * 4) + T - 1) / T;

    k_pre     <<<grid_node4, T>>>(x, W1l, W1r);
    k_scatter1<<<grid_edge4, T>>>(ei);
    k_node1   <<<grid_node4, T>>>(b1);
    k_scatter2<<<grid_edge4, T>>>(ei);
    k_node2   <<<grid_node4, T>>>(out, W2l, b2, W2r);
}

// round 8
// speedup vs baseline: 2.3564x; 1.5398x over previous
#include <cuda_runtime.h>

#define N_NODES 100000
#define N_EDGES 1600000
#define F_IN 32
#define HID 16

// Scratch (no allocations allowed in kernel_launch)
__device__ __align__(16) float g_deg [N_NODES];
__device__ __align__(16) float g_xt  [N_NODES * HID];   // x @ W1_l.T
__device__ __align__(16) float g_xr1 [N_NODES * HID];   // x @ W1_r.T
__device__ __align__(16) float g_sum1[N_NODES * HID];   // scatter target layer 1
__device__ __align__(16) float g_h   [N_NODES * HID];   // relu(layer1)
__device__ __align__(16) float g_sumh[N_NODES * HID];   // scatter target layer 2

__device__ __forceinline__ void red_add_v4(float* addr, float4 v) {
    asm volatile("red.global.add.v4.f32 [%0], {%1,%2,%3,%4};"
                 :: "l"(addr), "f"(v.x), "f"(v.y), "f"(v.z), "f"(v.w)
                 : "memory");
}

// ---------------------------------------------------------------------------
// 1) k_pre: 4 threads/node, TRANSPOSED smem weights (conflict-free LDS).
//    Thread q computes outputs [4q,4q+4) of xt = x@W1l.T and xr1 = x@W1r.T.
// ---------------------------------------------------------------------------
__global__ void __launch_bounds__(256) k_pre(const float* __restrict__ x,
                                             const float* __restrict__ W1l,
                                             const float* __restrict__ W1r) {
    __shared__ float Wl[F_IN * HID];   // Wl[k*HID + o] = W1l[o*F_IN + k]
    __shared__ float Wr[F_IN * HID];
    for (int i = threadIdx.x; i < HID * F_IN; i += blockDim.x) {
        int o = i >> 5;       // / F_IN
        int k = i & 31;       // % F_IN
        Wl[k * HID + o] = W1l[i];
        Wr[k * HID + o] = W1r[i];
    }
    __syncthreads();

    unsigned t = blockIdx.x * blockDim.x + threadIdx.x;
    unsigned n = t >> 2;
    unsigned q = t & 3;
    if (n >= N_NODES) return;

    if (q == 0) g_deg[n] = 0.0f;
    float4 z = make_float4(0.f, 0.f, 0.f, 0.f);
    *reinterpret_cast<float4*>(g_sum1 + (size_t)n * HID + q * 4) = z;
    *reinterpret_cast<float4*>(g_sumh + (size_t)n * HID + q * 4) = z;

    float xr[F_IN];
    const float4* xp = reinterpret_cast<const float4*>(x + (size_t)n * F_IN);
#pragma unroll
    for (int g = 0; g < F_IN / 4; g++) {
        float4 v = __ldg(xp + g);
        xr[4*g+0] = v.x; xr[4*g+1] = v.y; xr[4*g+2] = v.z; xr[4*g+3] = v.w;
    }

    float4 rt, rr;
    float* rtp = &rt.x;
    float* rrp = &rr.x;
#pragma unroll
    for (int oo = 0; oo < 4; oo++) {
        int o = q * 4 + oo;
        float at = 0.0f, ar = 0.0f;
#pragma unroll
        for (int k = 0; k < F_IN; k++) {
            at += xr[k] * Wl[k * HID + o];
            ar += xr[k] * Wr[k * HID + o];
        }
        rtp[oo] = at;
        rrp[oo] = ar;
    }
    *reinterpret_cast<float4*>(g_xt  + (size_t)n * HID + q * 4) = rt;
    *reinterpret_cast<float4*>(g_xr1 + (size_t)n * HID + q * 4) = rr;
}

// ---------------------------------------------------------------------------
// 2) edge scatter layer 1: sum1[dst] += xt[src]; deg[dst] += 1
//    4 threads per edge, one red.v4 each.
// ---------------------------------------------------------------------------
__global__ void k_scatter1(const int* __restrict__ ei) {
    unsigned t = blockIdx.x * blockDim.x + threadIdx.x;
    unsigned e = t >> 2;
    unsigned q = t & 3;
    if (e >= N_EDGES) return;
    int s = __ldg(ei + e);
    int d = __ldg(ei + N_EDGES + e);

    if (q == 0) atomicAdd(&g_deg[d], 1.0f);

    float4 v = *reinterpret_cast<const float4*>(g_xt + (size_t)s * HID + q * 4);
    red_add_v4(g_sum1 + (size_t)d * HID + q * 4, v);
}

// ---------------------------------------------------------------------------
// 3) h = relu(sum1/max(deg,1) + b1 + xr1)   — pure elementwise, quad/node
// ---------------------------------------------------------------------------
__global__ void k_node1(const float* __restrict__ b1) {
    unsigned t = blockIdx.x * blockDim.x + threadIdx.x;
    unsigned n = t >> 2;
    unsigned q = t & 3;
    if (n >= N_NODES) return;

    float inv = 1.0f / fmaxf(__ldg(&g_deg[n]), 1.0f);
    float4 s = *reinterpret_cast<const float4*>(g_sum1 + (size_t)n * HID + q * 4);
    float4 r = *reinterpret_cast<const float4*>(g_xr1  + (size_t)n * HID + q * 4);
    float4 b = __ldg(reinterpret_cast<const float4*>(b1) + q);

    float4 o;
    o.x = fmaxf(s.x * inv + b.x + r.x, 0.0f);
    o.y = fmaxf(s.y * inv + b.y + r.y, 0.0f);
    o.z = fmaxf(s.z * inv + b.z + r.z, 0.0f);
    o.w = fmaxf(s.w * inv + b.w + r.w, 0.0f);
    *reinterpret_cast<float4*>(g_h + (size_t)n * HID + q * 4) = o;
}

// ---------------------------------------------------------------------------
// 4) edge scatter layer 2: sumh[dst] += h[src]  (4 threads per edge)
// ---------------------------------------------------------------------------
__global__ void k_scatter2(const int* __restrict__ ei) {
    unsigned t = blockIdx.x * blockDim.x + threadIdx.x;
    unsigned e = t >> 2;
    unsigned q = t & 3;
    if (e >= N_EDGES) return;
    int s = __ldg(ei + e);
    int d = __ldg(ei + N_EDGES + e);

    float4 v = *reinterpret_cast<const float4*>(g_h + (size_t)s * HID + q * 4);
    red_add_v4(g_sumh + (size_t)d * HID + q * 4, v);
}

// ---------------------------------------------------------------------------
// 5) k_node2: 4 threads/node, TRANSPOSED smem weights.
//    Thread q computes outputs [8q, 8q+8) of
//    out = (sumh*inv) @ W2_l.T + b2 + h @ W2_r.T
// ---------------------------------------------------------------------------
__global__ void __launch_bounds__(256) k_node2(float* __restrict__ out,
                        const float* __restrict__ W2l,
                        const float* __restrict__ b2,
                        const float* __restrict__ W2r) {
    __shared__ float Wl[HID * F_IN];   // Wl[k*F_IN + f] = W2l[f*HID + k]
    __shared__ float Wr[HID * F_IN];
    __shared__ float bs[F_IN];
    for (int i = threadIdx.x; i < F_IN * HID; i += blockDim.x) {
        int f = i >> 4;      // / HID
        int k = i & 15;      // % HID
        Wl[k * F_IN + f] = W2l[i];
        Wr[k * F_IN + f] = W2r[i];
    }
    if (threadIdx.x < F_IN) bs[threadIdx.x] = b2[threadIdx.x];
    __syncthreads();

    unsigned t = blockIdx.x * blockDim.x + threadIdx.x;
    unsigned n = t >> 2;
    unsigned q = t & 3;
    if (n >= N_NODES) return;

    float inv = 1.0f / fmaxf(g_deg[n], 1.0f);

    float hr[HID], ar[HID];
    const float4* hp = reinterpret_cast<const float4*>(g_h    + (size_t)n * HID);
    const float4* ap = reinterpret_cast<const float4*>(g_sumh + (size_t)n * HID);
#pragma unroll
    for (int g = 0; g < HID / 4; g++) {
        float4 v = hp[g];
        hr[4*g+0] = v.x; hr[4*g+1] = v.y; hr[4*g+2] = v.z; hr[4*g+3] = v.w;
        float4 a = ap[g];
        ar[4*g+0] = a.x * inv; ar[4*g+1] = a.y * inv;
        ar[4*g+2] = a.z * inv; ar[4*g+3] = a.w * inv;
    }

    float4* op = reinterpret_cast<float4*>(out + (size_t)n * F_IN + q * 8);
#pragma unroll
    for (int fg = 0; fg < 2; fg++) {
        float4 r;
        float* rp = &r.x;
#pragma unroll
        for (int ff = 0; ff < 4; ff++) {
            int f = q * 8 + fg * 4 + ff;
            float acc = bs[f];
#pragma unroll
            for (int k = 0; k < HID; k++) {
                acc += ar[k] * Wl[k * F_IN + f] + hr[k] * Wr[k * F_IN + f];
            }
            rp[ff] = acc;
        }
        op[fg] = r;
    }
}

// ---------------------------------------------------------------------------
extern "C" void kernel_launch(void* const* d_in, const int* in_sizes, int n_in,
                              void* d_out, int out_size) {
    const float* x   = (const float*)d_in[0];
    const int*   ei  = (const int*)d_in[1];   // [1,2,E], int32 (JAX x64 off)
    const float* W1l = (const float*)d_in[2];
    const float* b1  = (const float*)d_in[3];
    const float* W1r = (const float*)d_in[4];
    const float* W2l = (const float*)d_in[5];
    const float* b2  = (const float*)d_in[6];
    const float* W2r = (const float*)d_in[7];
    float*       out = (float*)d_out;

    const int T = 256;
    const int grid_node4 = (N_NODES * 4 + T - 1) / T;
    const int grid_edge4 = ((N_EDGES * 4) + T - 1) / T;

    k_pre     <<<grid_node4, T>>>(x, W1l, W1r);
    k_scatter1<<<grid_edge4, T>>>(ei);
    k_node1   <<<grid_node4, T>>>(b1);
    k_scatter2<<<grid_edge4, T>>>(ei);
    k_node2   <<<grid_node4, T>>>(out, W2l, b2, W2r);
}

// round 9
// speedup vs baseline: 2.6291x; 1.1157x over previous
#include <cuda_runtime.h>

#define N_NODES 100000
#define N_EDGES 1600000
#define F_IN 32
#define HID 16

// Scratch (no allocations allowed in kernel_launch)
__device__ __align__(16) float g_deg [N_NODES];
__device__ __align__(16) float g_xt  [N_NODES * HID];   // x @ W1_l.T
__device__ __align__(16) float g_xr1 [N_NODES * HID];   // x @ W1_r.T
__device__ __align__(16) float g_sum1[N_NODES * HID];   // scatter target layer 1
__device__ __align__(16) float g_h   [N_NODES * HID];   // relu(layer1)
__device__ __align__(16) float g_sumh[N_NODES * HID];   // scatter target layer 2

__device__ __forceinline__ void red_add_v4(float* addr, float4 v) {
    asm volatile("red.global.add.v4.f32 [%0], {%1,%2,%3,%4};"
                 :: "l"(addr), "f"(v.x), "f"(v.y), "f"(v.z), "f"(v.w)
                 : "memory");
}

// ---------------------------------------------------------------------------
// 0) zero scratch (float4 stores; deg zeroed as float4 too)
// ---------------------------------------------------------------------------
__global__ void k_zero() {
    int i = blockIdx.x * blockDim.x + threadIdx.x;
    float4 z = make_float4(0.f, 0.f, 0.f, 0.f);
    if (i < N_NODES * HID / 4) {
        reinterpret_cast<float4*>(g_sum1)[i] = z;
        reinterpret_cast<float4*>(g_sumh)[i] = z;
    }
    if (i < N_NODES / 4) {
        reinterpret_cast<float4*>(g_deg)[i] = z;
    }
}

// ---------------------------------------------------------------------------
// 1) k_pre: 2 threads/node; lane parity m selects matrix (0:W1l->xt, 1:W1r->xr1).
//    Weights in smem, 528-float pad between copies (bank offset 16 => the two
//    broadcast groups never collide). Inner loop uses LDS.128 (1 LDS : 4 FFMA).
// ---------------------------------------------------------------------------
__global__ void __launch_bounds__(256) k_pre(const float* __restrict__ x,
                                             const float* __restrict__ W1l,
                                             const float* __restrict__ W1r) {
    __shared__ float WS[2 * 528];      // [0..511]=W1l, [528..1039]=W1r
    for (int i = threadIdx.x; i < HID * F_IN; i += blockDim.x) {
        WS[i]       = W1l[i];
        WS[528 + i] = W1r[i];
    }
    __syncthreads();

    unsigned t = blockIdx.x * blockDim.x + threadIdx.x;
    unsigned n = t >> 1;
    unsigned m = t & 1;
    if (n >= N_NODES) return;

    float xr[F_IN];
    const float4* xp = reinterpret_cast<const float4*>(x + (size_t)n * F_IN);
#pragma unroll
    for (int g = 0; g < F_IN / 4; g++) {
        float4 v = __ldg(xp + g);
        xr[4*g+0] = v.x; xr[4*g+1] = v.y; xr[4*g+2] = v.z; xr[4*g+3] = v.w;
    }

    const float4* ws4 = reinterpret_cast<const float4*>(WS + m * 528);

    float ov[HID];
#pragma unroll
    for (int o = 0; o < HID; o++) {
        float acc = 0.0f;
#pragma unroll
        for (int kg = 0; kg < F_IN / 4; kg++) {
            float4 w = ws4[o * (F_IN / 4) + kg];
            acc += xr[4*kg+0] * w.x + xr[4*kg+1] * w.y
                 + xr[4*kg+2] * w.z + xr[4*kg+3] * w.w;
        }
        ov[o] = acc;
    }

    float* dst = (m == 0 ? g_xt : g_xr1) + (size_t)n * HID;
    float4* dp = reinterpret_cast<float4*>(dst);
#pragma unroll
    for (int g = 0; g < HID / 4; g++) {
        dp[g] = make_float4(ov[4*g+0], ov[4*g+1], ov[4*g+2], ov[4*g+3]);
    }
}

// ---------------------------------------------------------------------------
// 2) edge scatter layer 1: sum1[dst] += xt[src]; deg[dst] += 1
//    4 threads per edge, one red.v4 each.
// ---------------------------------------------------------------------------
__global__ void k_scatter1(const int* __restrict__ ei) {
    unsigned t = blockIdx.x * blockDim.x + threadIdx.x;
    unsigned e = t >> 2;
    unsigned q = t & 3;
    if (e >= N_EDGES) return;
    int s = __ldg(ei + e);
    int d = __ldg(ei + N_EDGES + e);

    if (q == 0) atomicAdd(&g_deg[d], 1.0f);

    float4 v = *reinterpret_cast<const float4*>(g_xt + (size_t)s * HID + q * 4);
    red_add_v4(g_sum1 + (size_t)d * HID + q * 4, v);
}

// ---------------------------------------------------------------------------
// 3) h = relu(sum1/max(deg,1) + b1 + xr1)   — pure elementwise, quad/node
// ---------------------------------------------------------------------------
__global__ void k_node1(const float* __restrict__ b1) {
    unsigned t = blockIdx.x * blockDim.x + threadIdx.x;
    unsigned n = t >> 2;
    unsigned q = t & 3;
    if (n >= N_NODES) return;

    float inv = 1.0f / fmaxf(__ldg(&g_deg[n]), 1.0f);
    float4 s = *reinterpret_cast<const float4*>(g_sum1 + (size_t)n * HID + q * 4);
    float4 r = *reinterpret_cast<const float4*>(g_xr1  + (size_t)n * HID + q * 4);
    float4 b = __ldg(reinterpret_cast<const float4*>(b1) + q);

    float4 o;
    o.x = fmaxf(s.x * inv + b.x + r.x, 0.0f);
    o.y = fmaxf(s.y * inv + b.y + r.y, 0.0f);
    o.z = fmaxf(s.z * inv + b.z + r.z, 0.0f);
    o.w = fmaxf(s.w * inv + b.w + r.w, 0.0f);
    *reinterpret_cast<float4*>(g_h + (size_t)n * HID + q * 4) = o;
}

// ---------------------------------------------------------------------------
// 4) edge scatter layer 2: sumh[dst] += h[src]  (4 threads per edge)
// ---------------------------------------------------------------------------
__global__ void k_scatter2(const int* __restrict__ ei) {
    unsigned t = blockIdx.x * blockDim.x + threadIdx.x;
    unsigned e = t >> 2;
    unsigned q = t & 3;
    if (e >= N_EDGES) return;
    int s = __ldg(ei + e);
    int d = __ldg(ei + N_EDGES + e);

    float4 v = *reinterpret_cast<const float4*>(g_h + (size_t)s * HID + q * 4);
    red_add_v4(g_sumh + (size_t)d * HID + q * 4, v);
}

// ---------------------------------------------------------------------------
// 5) k_node2: 1 thread/node (lanes-as-nodes, uniform weight broadcasts),
//    LDS.128 weight reads.  out = (sumh*inv)@W2_l.T + b2 + h@W2_r.T
// ---------------------------------------------------------------------------
__global__ void __launch_bounds__(256) k_node2(float* __restrict__ out,
                        const float* __restrict__ W2l,
                        const float* __restrict__ b2,
                        const float* __restrict__ W2r) {
    __shared__ float Wl[F_IN * HID];
    __shared__ float Wr[F_IN * HID];
    __shared__ float bs[F_IN];
    for (int i = threadIdx.x; i < F_IN * HID; i += blockDim.x) {
        Wl[i] = W2l[i];
        Wr[i] = W2r[i];
    }
    if (threadIdx.x < F_IN) bs[threadIdx.x] = b2[threadIdx.x];
    __syncthreads();

    int n = blockIdx.x * blockDim.x + threadIdx.x;
    if (n >= N_NODES) return;

    float inv = 1.0f / fmaxf(g_deg[n], 1.0f);

    float hr[HID], ar[HID];
    const float4* hp = reinterpret_cast<const float4*>(g_h    + (size_t)n * HID);
    const float4* ap = reinterpret_cast<const float4*>(g_sumh + (size_t)n * HID);
#pragma unroll
    for (int g = 0; g < HID / 4; g++) {
        float4 v = hp[g];
        hr[4*g+0] = v.x; hr[4*g+1] = v.y; hr[4*g+2] = v.z; hr[4*g+3] = v.w;
        float4 a = ap[g];
        ar[4*g+0] = a.x * inv; ar[4*g+1] = a.y * inv;
        ar[4*g+2] = a.z * inv; ar[4*g+3] = a.w * inv;
    }

    const float4* Wl4 = reinterpret_cast<const float4*>(Wl);
    const float4* Wr4 = reinterpret_cast<const float4*>(Wr);

    float4* op = reinterpret_cast<float4*>(out + (size_t)n * F_IN);
#pragma unroll
    for (int fg = 0; fg < F_IN / 4; fg++) {
        float4 r;
        float* rp = &r.x;
#pragma unroll
        for (int ff = 0; ff < 4; ff++) {
            int f = fg * 4 + ff;
            float acc = bs[f];
#pragma unroll
            for (int kg = 0; kg < HID / 4; kg++) {
                float4 wl = Wl4[f * (HID / 4) + kg];
                float4 wr = Wr4[f * (HID / 4) + kg];
                acc += ar[4*kg+0] * wl.x + ar[4*kg+1] * wl.y
                     + ar[4*kg+2] * wl.z + ar[4*kg+3] * wl.w
                     + hr[4*kg+0] * wr.x + hr[4*kg+1] * wr.y
                     + hr[4*kg+2] * wr.z + hr[4*kg+3] * wr.w;
            }
            rp[ff] = acc;
        }
        op[fg] = r;
    }
}

// ---------------------------------------------------------------------------
extern "C" void kernel_launch(void* const* d_in, const int* in_sizes, int n_in,
                              void* d_out, int out_size) {
    const float* x   = (const float*)d_in[0];
    const int*   ei  = (const int*)d_in[1];   // [1,2,E], int32 (JAX x64 off)
    const float* W1l = (const float*)d_in[2];
    const float* b1  = (const float*)d_in[3];
    const float* W1r = (const float*)d_in[4];
    const float* W2l = (const float*)d_in[5];
    const float* b2  = (const float*)d_in[6];
    const float* W2r = (const float*)d_in[7];
    float*       out = (float*)d_out;

    const int T = 256;
    const int grid_zero  = (N_NODES * HID / 4 + T - 1) / T;
    const int grid_node  = (N_NODES + T - 1) / T;
    const int grid_node2 = (N_NODES * 2 + T - 1) / T;
    const int grid_node4 = (N_NODES * 4 + T - 1) / T;
    const int grid_edge4 = ((N_EDGES * 4) + T - 1) / T;

    k_zero    <<<grid_zero,  T>>>();
    k_pre     <<<grid_node2, T>>>(x, W1l, W1r);
    k_scatter1<<<grid_edge4, T>>>(ei);
    k_node1   <<<grid_node4, T>>>(b1);
    k_scatter2<<<grid_edge4, T>>>(ei);
    k_node2   <<<grid_node,  T>>>(out, W2l, b2, W2r);
}